// round 17
// baseline (speedup 1.0000x reference)
#include <cuda_runtime.h>
#include <cuda_fp16.h>

// ---------------------------------------------------------------------------
// SSIM (16,3,512,512) fp32, 11x11 Gaussian (sigma=1.5), zero pad, global mean.
// R17 = R16 fused skeleton + FP16X2 TAP STORAGE: TRANS converts (x,y) ->
// (S,D) = (x+y, x-y) rounded to one __half2 (4B) in a ping-pong tap buffer;
// horizontal taps are 11 LDS.32 (11 wavefronts) instead of 11 LDS.64 (22) --
// the measured L1TEX wall. All accumulation stays f32x2 (taps converted via
// two F2F half-selects + pack per use). Ring/extraction/pipeline unchanged.
// ---------------------------------------------------------------------------

#define IMW     512
#define IMH     512
#define NT      512                 // one thread per column
#define TH      171                 // output rows per band (3 bands cover 512)
#define NBANDS  3
#define NPLANES 48                  // 16 * 3
#define NBLOCKS (NPLANES * NBANDS)  // 144 CTAs -> single wave
#define SSIM_C1 0.0001f
#define SSIM_C2 0.0009f

typedef unsigned long long ull;

__device__ float        g_partials[NBLOCKS];
__device__ unsigned int g_count;    // zero-init; reset by last block each run

#define CPA4(daddr, sptr) \
    asm volatile("cp.async.ca.shared.global [%0], [%1], 4;" \
                 :: "r"(daddr), "l"(sptr))
#define CPA4T(daddr, sptr) \
    asm volatile("cp.async.ca.shared.global [%0+256], [%1+128], 4;" \
                 :: "r"(daddr), "l"(sptr))
#define CPA_COMMIT() asm volatile("cp.async.commit_group;" ::: "memory")
#define CPA_WAIT2()  asm volatile("cp.async.wait_group 2;"  ::: "memory")
#define CPA_WAIT0()  asm volatile("cp.async.wait_group 0;"  ::: "memory")

#define MUL2(d, a, b) \
    asm("mul.rn.f32x2 %0, %1, %2;" : "=l"(d) : "l"(a), "l"(b))
#define ADD2(d, a, b) \
    asm("add.rn.f32x2 %0, %1, %2;" : "=l"(d) : "l"(a), "l"(b))
#define FMA2ACC(acc, a, b) \
    asm("fma.rn.f32x2 %0, %1, %2, %0;" : "+l"(acc) : "l"(a), "l"(b))
#define UNPACK2(lo, hi, s) \
    asm("mov.b64 {%0, %1}, %2;" : "=f"(lo), "=f"(hi) : "l"(s))
#define PACK2(d, lo, hi) \
    asm("mov.b64 %0, {%1, %2};" : "=l"(d) : "f"(lo), "f"(hi))

// Symmetric weight-pair index: W[d] == W[10-d], only 6 registers needed.
#define WIDX(d) ((d) <= 5 ? (d) : 10 - (d))

// Transform row rn: raw (x,y) f32 pairs -> fp16x2 (S,D) in tap[rn&1].
#define TRANSROW(rn) do {                                                     \
    const int rb_ = (rn) & 7;                                                 \
    const int tb_ = (rn) & 1;                                                 \
    {                                                                         \
        const float2 v = seg[rb_][w][l];                                      \
        tap[tb_][w][l] = __floats2half2_rn(v.x + v.y, v.x - v.y);             \
    }                                                                         \
    if (tailst) {                                                             \
        const float2 u = seg[rb_][w][32 + l];                                 \
        tap[tb_][w][32 + l] = __floats2half2_rn(u.x + u.y, u.x - u.y);        \
    }                                                                         \
} while (0)

// Load + convert the 11 taps of row rn into ull array TP (f32x2 pairs).
#define ROWLOADT(rn, TP) do {                                                 \
    const __half2* tr_ = &tap[(rn) & 1][w][l];                                \
    _Pragma("unroll")                                                         \
    for (int k = 0; k < 11; ++k) {                                            \
        const __half2 h_ = tr_[k];                                            \
        const float lo_ = __low2float(h_);                                    \
        const float hi_ = __high2float(h_);                                   \
        PACK2((TP)[k], lo_, hi_);                                             \
    }                                                                         \
} while (0)

// h-conv + ring + extraction for row ir_, taps in TP.
// P must be a compile-time constant == ir_ mod 11.
#define ROWMATH(P, ir_, TP) do {                                              \
    ull hpq, hsd, tc;                                                         \
    MUL2(hpq, (TP)[5], W2[5]);                                                \
    MUL2(tc,  (TP)[5], (TP)[5]);                                              \
    MUL2(hsd, tc, W2[5]);                                                     \
    _Pragma("unroll")                                                         \
    for (int k = 0; k < 5; ++k) {   /* symmetric pairs (k, 10-k) */           \
        ull ab, sq;                                                           \
        ADD2(ab, (TP)[k], (TP)[10 - k]);                                      \
        FMA2ACC(hpq, ab, W2[k]);                                              \
        MUL2(sq, (TP)[k], (TP)[k]);                                           \
        FMA2ACC(sq, (TP)[10 - k], (TP)[10 - k]);                              \
        FMA2ACC(hsd, sq, W2[k]);                                              \
    }                                                                         \
    _Pragma("unroll")                                                         \
    for (int s = 0; s < 11; ++s) {                                            \
        const int d = ((P) - s + 11) % 11;      /* compile-time */            \
        if (s == (P)) {     /* tap d==0: new output starts -> overwrite */    \
            MUL2(APQ[s], hpq, W2[0]);                                         \
            MUL2(ASD[s], hsd, W2[0]);                                         \
        } else {                                                              \
            FMA2ACC(APQ[s], hpq, W2[WIDX(d)]);                                \
            FMA2ACC(ASD[s], hsd, W2[WIDX(d)]);                                \
        }                                                                     \
    }                                                                         \
    const int e_ = ((P) + 1) % 11;              /* compile-time */            \
    if ((ir_) >= 10) {          /* output row m = ir-10 is real */            \
        float p, q, sv, dv;                                                   \
        UNPACK2(p, q, APQ[e_]);                                               \
        UNPACK2(sv, dv, ASD[e_]);                                             \
        const float a2 = p * p;                                               \
        const float b2 = q * q;                                               \
        const float U  = a2 + b2;                                             \
        const float V  = a2 - b2;                                             \
        const float M  = sv + dv;                                             \
        const float N2 = sv - dv;                                             \
        const float t1 = 0.5f * V + SSIM_C1;                                  \
        const float t2 = 0.5f * (N2 - V) + SSIM_C2;                           \
        const float t3 = 0.5f * U + SSIM_C1;                                  \
        const float t4 = 0.5f * (M - U) + SSIM_C2;                            \
        ssum += __fdividef(t1 * t2, t3 * t4);                                 \
    }                                                                         \
} while (0)

// Fused guard-free phase: rows IRA, IRA+1 (IRA <= 174; fills reach <= 179).
// Tap ping-pong: rows ira, ira+1 use tap buffers ira&1, (ira+1)&1 (distinct),
// written and read within this phase only.
#define PHASE2F(PA, PB, IRA) do {                                             \
    const int ira_ = (IRA);                                                   \
    CPA_WAIT2();               /* raw rows <= ira_+1 complete */              \
    TRANSROW(ira_);                                                           \
    TRANSROW(ira_ + 1);                                                       \
    FILLF(ira_ + 4); CPA_COMMIT();                                            \
    FILLF(ira_ + 5); CPA_COMMIT();                                            \
    __syncwarp();                                                             \
    ull tpA[11], tpB[11];                                                     \
    ROWLOADT(ira_,     tpA);                                                  \
    ROWLOADT(ira_ + 1, tpB);                                                  \
    ROWMATH(PA, ira_,     tpA);                                               \
    ROWMATH(PB, ira_ + 1, tpB);                                               \
} while (0)

// Guarded tail phase (rows 176..nrows-1), exact wait.
#define PHASET(P, IRV) do {                                                   \
    const int irt_ = (IRV);                                                   \
    if (irt_ < nrows) {                                                       \
        if (irt_ + 3 < nrows) FILLF(irt_ + 3);                                \
        CPA_COMMIT();                                                         \
        CPA_WAIT0();                                                          \
        TRANSROW(irt_);                                                       \
        __syncwarp();                                                         \
        ull tpA[11];                                                          \
        ROWLOADT(irt_, tpA);                                                  \
        ROWMATH(P, irt_, tpA);                                                \
    }                                                                         \
} while (0)

__global__ void __launch_bounds__(NT, 1)
ssim_main(const float* __restrict__ img1, const float* __restrict__ img2,
          float* __restrict__ out)
{
    // Normalized 1D Gaussian, sigma=1.5, 11 taps (symmetric)
    const float W[6] = {
        0.00102838f, 0.00759874f, 0.03600077f, 0.10936069f, 0.21300553f,
        0.26601180f
    };
    // Duplicated 64-bit weight pairs (w|w); symmetry => 6 registers.
    ull W2[6];
#pragma unroll
    for (int k = 0; k < 6; ++k) {
        const unsigned u = __float_as_uint(W[k]);
        W2[k] = ((ull)u << 32) | (ull)u;
    }

    const int band  = blockIdx.x;           // 0..2
    const int plane = blockIdx.y;           // 0..47
    const int t     = threadIdx.x;          // column 0..511
    const int l     = t & 31;               // lane
    const int w     = t >> 5;               // warp
    const int r0    = band * TH;
    const int rows  = (IMH - r0 < TH) ? (IMH - r0) : TH;   // 171/171/170
    const int nrows = rows + 10;            // 181/181/180
    const int pbase = plane * (IMW * IMH);

    // Warp-private 8-deep rotating RAW halo segments (x, y) from cp.async.
    __shared__ float2 seg[8][16][44];
    // Ping-pong fp16x2 (S,D) tap buffers (written + read in one phase).
    __shared__ __half2 tap[2][16][44];

    // Static ring (packed): slot s <-> output rows m with m % 11 == s.
    ull APQ[11], ASD[11];
#pragma unroll
    for (int j = 0; j < 11; ++j) { APQ[j] = 0ULL; ASD[j] = 0ULL; }

    // Column mapping:
    //   slot j = l      <-> col t - 5   (valid iff t >= 5)
    //   slot j = 32 + l <-> col t + 27  (exists iff l < 10, valid iff < 512)
    const bool mainok = (t >= 5);
    const bool tailst = (l < 10);
    const bool tailok = tailst && (t + 27 < IMW);

    // Base pointers for this lane's main column (col t-5), row gr=0.
    const float* bp1 = img1 + pbase + (t - 5);
    const float* bp2 = img2 + pbase + (t - 5);

    // u32 shared address of this warp+lane's RAW slot in buffer 0
    unsigned sbu;
    asm("{ .reg .u64 tt; cvta.to.shared.u64 tt, %1; cvt.u32.u64 %0, tt; }"
        : "=r"(sbu) : "l"(&seg[0][w][l]));
    const unsigned BSTRIDE = 16u * 44u * 8u;   // bytes per raw buffer (5632)

    auto FILLF = [&](int rn) {
        const int gr = r0 - 5 + rn;             // global row (zero pad if OOB)
        const unsigned d = sbu + (unsigned)(rn & 7) * BSTRIDE;
        if ((unsigned)gr < (unsigned)IMH) {
            const float* p1 = bp1 + gr * IMW;   // one IMAD.WIDE each
            const float* p2 = bp2 + gr * IMW;
            if (mainok) { CPA4(d, p1);       CPA4(d + 4u, p2); }
            if (tailok) { CPA4T(d, p1);      CPA4T(d + 4u, p2); }
        } else {
            const float z = 0.f;
            asm volatile("st.shared.v2.f32 [%0], {%1,%1};" :: "r"(d), "f"(z));
            if (tailst)
                asm volatile("st.shared.v2.f32 [%0+256], {%1,%1};"
                             :: "r"(d), "f"(z));
        }
    };

    // Pre-zero raw slots never written by cp.async (col-invalid); all buffers.
    // (TRANS reads these zeros and writes fp16 zeros -> padding preserved.)
#pragma unroll
    for (int b = 0; b < 8; ++b) {
        if (!mainok)           seg[b][w][l]      = make_float2(0.f, 0.f);
        if (tailst && !tailok) seg[b][w][32 + l] = make_float2(0.f, 0.f);
    }

    // Prologue: rows 0..3 in flight as four groups.
    FILLF(0); CPA_COMMIT();
    FILLF(1); CPA_COMMIT();
    FILLF(2); CPA_COMMIT();
    FILLF(3); CPA_COMMIT();

    float ssum = 0.f;

    // 8 blocks of 11 fused phases: rows 0..175 (fills reach row 179).
#pragma unroll 1
    for (int base = 0; base < 176; base += 22) {
#pragma unroll
        for (int i = 0; i < 11; ++i) {
            PHASE2F((2 * i) % 11, (2 * i + 1) % 11, base + 2 * i);
        }
    }
    // Guarded tail: rows 176..nrows-1 (176 % 11 == 0 -> P == q).
    {
#pragma unroll
        for (int q = 0; q < 5; ++q) {
            PHASET(q, 176 + q);
        }
    }

    // ---- deterministic block reduction ----
    __syncthreads();
#pragma unroll
    for (int off = 16; off; off >>= 1)
        ssum += __shfl_xor_sync(0xffffffffu, ssum, off);

    __shared__ float wsum[16];
    __shared__ bool  islast;
    if (l == 0) wsum[w] = ssum;
    __syncthreads();
    if (t == 0) {
        float v = 0.f;
#pragma unroll
        for (int i = 0; i < 16; ++i) v += wsum[i];
        g_partials[plane * NBANDS + band] = v;
        __threadfence();
        const unsigned n = atomicAdd(&g_count, 1u);
        islast = (n == (unsigned)(NBLOCKS - 1));
    }
    __syncthreads();

    // ---- last CTA: fixed-order (deterministic) final reduction ----
    if (islast) {
        __threadfence();
        float v = (t < NBLOCKS) ? g_partials[t] : 0.f;
#pragma unroll
        for (int off = 16; off; off >>= 1)
            v += __shfl_xor_sync(0xffffffffu, v, off);
        if (l == 0) wsum[w] = v;
        __syncthreads();
        if (t == 0) {
            float s = 0.f;
#pragma unroll
            for (int i = 0; i < 16; ++i) s += wsum[i];
            out[0] = s * (1.0f / 12582912.0f);  // / (16*3*512*512)
            g_count = 0u;                        // reset for next graph replay
        }
    }
}

extern "C" void kernel_launch(void* const* d_in, const int* in_sizes, int n_in,
                              void* d_out, int out_size)
{
    const float* img1 = (const float*)d_in[0];
    const float* img2 = (const float*)d_in[1];
    (void)in_sizes; (void)n_in; (void)out_size;

    dim3 grid(NBANDS, NPLANES);
    ssim_main<<<grid, NT>>>(img1, img2, (float*)d_out);
}